// round 9
// baseline (speedup 1.0000x reference)
#include <cuda_runtime.h>
#include <math.h>

#define NN 50000
#define EE 800000
#define D  64
#define GG 64
#define BN_EPS 1e-5f
#define SCAN_BLOCKS 196          // ceil(50000/256)
#define NTILES 782               // ceil(50000/64)

// ---------------- device scratch (device-code access only) ----------------
__device__ int   g_degi  [NN];            // zero at load; re-zeroed in scan23 phase
__device__ float g_dinv  [NN];
__device__ int   g_rowptr[NN + 1];
__device__ int   g_cursor[NN];
__device__ int   g_blocksum[256];
__device__ __align__(16) int2  g_csr[EE + NN];   // (src, dinv[src] bits), even-padded
__device__ __align__(16) float g_h1 [NN * D];
__device__ __align__(16) float g_agg[NN * D];
__device__ __align__(16) float g_h2 [NN * D];
__device__ float g_bnsum[D];
__device__ float g_bnsq [D];
__device__ __align__(16) float g_pool[GG * D];
__device__ float g_cnt [GG];

// ---------------- software grid barrier ----------------
__device__ int           g_bar_cnt = 0;
__device__ volatile int  g_bar_gen = 0;

__device__ __forceinline__ void gbar() {
    __threadfence();
    __syncthreads();
    if (threadIdx.x == 0) {
        int gen = g_bar_gen;
        if (atomicAdd(&g_bar_cnt, 1) == (int)gridDim.x - 1) {
            g_bar_cnt = 0;
            __threadfence();
            g_bar_gen = gen + 1;
        } else {
            while (g_bar_gen == gen) { __nanosleep(64); }
            __threadfence();
        }
    }
    __syncthreads();
}

// ---------------- packed f32x2 helpers ----------------
__device__ __forceinline__ unsigned long long pack2(float x, float y) {
    unsigned long long r;
    asm("mov.b64 %0, {%1, %2};" : "=l"(r) : "f"(x), "f"(y));
    return r;
}
__device__ __forceinline__ void ffma2(unsigned long long& d,
                                      unsigned long long a, unsigned long long b) {
    asm("fma.rn.f32x2 %0, %1, %2, %0;" : "+l"(d) : "l"(a), "l"(b));
}
__device__ __forceinline__ float2 unpack2(unsigned long long v) {
    float2 f;
    asm("mov.b64 {%0, %1}, %2;" : "=f"(f.x), "=f"(f.y) : "l"(v));
    return f;
}

// ---------------- shared memory union (phases reuse the same bytes) ----------------
struct GemmSmem { float sX[64][65]; float sW[64][64]; float scale[64]; float shift[64]; };
struct ScanSmem { int s[256]; int sb[256]; };
struct AggSmem  { float s_sum[64]; float s_sq[64]; };
union  SmemU    { GemmSmem g; ScanSmem sc; AggSmem a; };

// ---------------- GEMM tile: Y[tile*64 .. +64, :] = X @ W (+ optional BN/ELU) --------
template<int MODE>
__device__ void gemm_tile(int tile, const float* __restrict__ X,
                          const float* __restrict__ W, float* __restrict__ Y,
                          SmemU& sm) {
    __syncthreads();                       // protect smem reuse across tiles/phases
    int tid = threadIdx.x;
    int tx = tid & 15, ty = tid >> 4;
    int row0 = tile * 64;

    #pragma unroll
    for (int t = tid * 4; t < 4096; t += 1024)
        *(float4*)(&sm.g.sW[t >> 6][t & 63]) = *(const float4*)(W + t);
    #pragma unroll
    for (int t = tid * 4; t < 4096; t += 1024) {
        int r = t >> 6, c = t & 63;
        float4 v = make_float4(0.f, 0.f, 0.f, 0.f);
        if (row0 + r < NN) v = *(const float4*)(X + (size_t)(row0 + r) * D + c);
        if (MODE == 1) {
            v.x = v.x * sm.g.scale[c]     + sm.g.shift[c];
            v.y = v.y * sm.g.scale[c + 1] + sm.g.shift[c + 1];
            v.z = v.z * sm.g.scale[c + 2] + sm.g.shift[c + 2];
            v.w = v.w * sm.g.scale[c + 3] + sm.g.shift[c + 3];
            v.x = (v.x > 0.f) ? v.x : (__expf(v.x) - 1.0f);
            v.y = (v.y > 0.f) ? v.y : (__expf(v.y) - 1.0f);
            v.z = (v.z > 0.f) ? v.z : (__expf(v.z) - 1.0f);
            v.w = (v.w > 0.f) ? v.w : (__expf(v.w) - 1.0f);
        }
        sm.g.sX[r][c] = v.x; sm.g.sX[r][c + 1] = v.y;
        sm.g.sX[r][c + 2] = v.z; sm.g.sX[r][c + 3] = v.w;
    }
    __syncthreads();

    float acc[4][4] = {};
    int c0 = tx * 4, r0 = ty * 4;
    #pragma unroll 16
    for (int k = 0; k < 64; k++) {
        float4 w = *(const float4*)(&sm.g.sW[k][c0]);
        #pragma unroll
        for (int r = 0; r < 4; r++) {
            float xv = sm.g.sX[r0 + r][k];
            acc[r][0] += xv * w.x; acc[r][1] += xv * w.y;
            acc[r][2] += xv * w.z; acc[r][3] += xv * w.w;
        }
    }
    #pragma unroll
    for (int r = 0; r < 4; r++) {
        int row = row0 + r0 + r;
        if (row < NN)
            *(float4*)(Y + (size_t)row * D + c0) =
                make_float4(acc[r][0], acc[r][1], acc[r][2], acc[r][3]);
    }
}

// ---------------- aggregation over grid-strided nodes (R8 proven inner loop) ---------
// MODE 0: h=g_h1 -> g_agg, BN stats accumulated in registers then block-reduced once.
// MODE 1: h=g_h2 -> outp, fused global-mean-pool atomics.
template<int MODE>
__device__ void agg_nodes(const float* __restrict__ h, float* __restrict__ dstbuf,
                          const float* __restrict__ bias, const int* __restrict__ batch,
                          SmemU& sm) {
    int warp = threadIdx.x >> 5;
    int lane = threadIdx.x & 31;
    int half = lane >> 4;
    int fl   = lane & 15;
    int nw   = gridDim.x * 8;

    float4 bv = ((const float4*)bias)[fl];
    float bns[4] = {0.f, 0.f, 0.f, 0.f};
    float bnq[4] = {0.f, 0.f, 0.f, 0.f};

    for (int n = blockIdx.x * 8 + warp; n < NN; n += nw) {
        int e0 = g_rowptr[n];
        int e1 = g_rowptr[n + 1];          // padded even

        unsigned long long a0 = 0ull, a1 = 0ull;
        #pragma unroll 4
        for (int e = e0 + half; e < e1; e += 2) {
            int2 ec = g_csr[e];
            float c = __int_as_float(ec.y);              // dinv[src]
            float4 v = ((const float4*)h)[(size_t)ec.x * 16 + fl];
            unsigned long long cc = pack2(c, c);
            ffma2(a0, cc, pack2(v.x, v.y));
            ffma2(a1, cc, pack2(v.z, v.w));
        }
        float2 f0 = unpack2(a0), f1 = unpack2(a1);
        float4 acc = make_float4(f0.x, f0.y, f1.x, f1.y);
        acc.x += __shfl_xor_sync(0xffffffffu, acc.x, 16);
        acc.y += __shfl_xor_sync(0xffffffffu, acc.y, 16);
        acc.z += __shfl_xor_sync(0xffffffffu, acc.z, 16);
        acc.w += __shfl_xor_sync(0xffffffffu, acc.w, 16);

        if (half == 0) {
            float di = g_dinv[n];
            float cs = di * di;
            float4 hv = ((const float4*)h)[(size_t)n * 16 + fl];
            acc.x = fmaf(di, acc.x, fmaf(cs, hv.x, bv.x));
            acc.y = fmaf(di, acc.y, fmaf(cs, hv.y, bv.y));
            acc.z = fmaf(di, acc.z, fmaf(cs, hv.z, bv.z));
            acc.w = fmaf(di, acc.w, fmaf(cs, hv.w, bv.w));
            ((float4*)dstbuf)[(size_t)n * 16 + fl] = acc;

            if (MODE == 0) {
                bns[0] += acc.x; bns[1] += acc.y; bns[2] += acc.z; bns[3] += acc.w;
                bnq[0] += acc.x * acc.x; bnq[1] += acc.y * acc.y;
                bnq[2] += acc.z * acc.z; bnq[3] += acc.w * acc.w;
            } else {
                int g = batch[n];
                if (fl == 0) atomicAdd(&g_cnt[g], 1.0f);
                atomicAdd(((float4*)g_pool) + (size_t)g * 16 + fl, acc);
            }
        }
    }

    if (MODE == 0) {   // one block-level BN reduction for the whole phase
        __syncthreads();
        if (threadIdx.x < 64) { sm.a.s_sum[threadIdx.x] = 0.f; sm.a.s_sq[threadIdx.x] = 0.f; }
        __syncthreads();
        if (half == 0) {
            #pragma unroll
            for (int i = 0; i < 4; i++) {
                atomicAdd(&sm.a.s_sum[fl * 4 + i], bns[i]);
                atomicAdd(&sm.a.s_sq [fl * 4 + i], bnq[i]);
            }
        }
        __syncthreads();
        if (threadIdx.x < 64) {
            atomicAdd(&g_bnsum[threadIdx.x], sm.a.s_sum[threadIdx.x]);
            atomicAdd(&g_bnsq [threadIdx.x], sm.a.s_sq [threadIdx.x]);
        }
    }
}

// ---------------- the mega kernel ----------------
__global__ void __launch_bounds__(256)
mega_kernel(const float* __restrict__ x,
            const int* __restrict__ src, const int* __restrict__ dst,
            const int* __restrict__ batch,
            const float* __restrict__ W1, const float* __restrict__ b1,
            const float* __restrict__ gamma, const float* __restrict__ beta,
            const float* __restrict__ W2, const float* __restrict__ b2,
            float* __restrict__ out) {
    __shared__ SmemU sm;
    int tid    = threadIdx.x;
    int gtid   = blockIdx.x * 256 + tid;
    int stride = gridDim.x * 256;

    // ---- Phase 0: zero accumulators + degree count + GEMM-1 ----
    for (int i = gtid; i < GG * D; i += stride) g_pool[i] = 0.f;
    for (int i = gtid; i < D;      i += stride) { g_bnsum[i] = 0.f; g_bnsq[i] = 0.f; }
    for (int i = gtid; i < GG;     i += stride) g_cnt[i] = 0.f;
    for (int t = gtid; t < EE / 4; t += stride) {
        int4 d4 = ((const int4*)dst)[t];
        atomicAdd(&g_degi[d4.x], 1);
        atomicAdd(&g_degi[d4.y], 1);
        atomicAdd(&g_degi[d4.z], 1);
        atomicAdd(&g_degi[d4.w], 1);
    }
    for (int tile = blockIdx.x; tile < NTILES; tile += gridDim.x)
        gemm_tile<0>(tile, x, W1, g_h1, sm);
    gbar();

    // ---- Phase 1: scan1 (padded block sums + dinv) ----
    for (int c = blockIdx.x; c < SCAN_BLOCKS; c += gridDim.x) {
        __syncthreads();
        int idx = c * 256 + tid;
        int dv = (idx < NN) ? g_degi[idx] : 0;
        if (idx < NN) g_dinv[idx] = rsqrtf((float)dv + 1.0f);
        sm.sc.s[tid] = (dv + 1) & ~1;
        __syncthreads();
        for (int o = 128; o > 0; o >>= 1) {
            if (tid < o) sm.sc.s[tid] += sm.sc.s[tid + o];
            __syncthreads();
        }
        if (tid == 0) g_blocksum[c] = sm.sc.s[0];
    }
    gbar();

    // ---- Phase 2: scan23 (rowptr/cursor, pad entries, degi reset) ----
    for (int c = blockIdx.x; c < SCAN_BLOCKS; c += gridDim.x) {
        __syncthreads();
        sm.sc.sb[tid] = (tid < SCAN_BLOCKS) ? g_blocksum[tid] : 0;
        __syncthreads();
        for (int o = 1; o < 256; o <<= 1) {
            int a = (tid >= o) ? sm.sc.sb[tid - o] : 0;
            __syncthreads();
            sm.sc.sb[tid] += a;
            __syncthreads();
        }
        int blockoff = (c == 0) ? 0 : sm.sc.sb[c - 1];
        int idx = c * 256 + tid;
        int v  = (idx < NN) ? g_degi[idx] : 0;
        int vp = (v + 1) & ~1;
        sm.sc.s[tid] = vp;
        __syncthreads();
        for (int o = 1; o < 256; o <<= 1) {
            int a = (tid >= o) ? sm.sc.s[tid - o] : 0;
            __syncthreads();
            sm.sc.s[tid] += a;
            __syncthreads();
        }
        if (idx < NN) {
            int rp = blockoff + sm.sc.s[tid] - vp;
            g_rowptr[idx] = rp;
            g_cursor[idx] = rp;
            if (v & 1) g_csr[rp + v] = make_int2(0, 0);
            g_degi[idx] = 0;                       // invariant for next call
            if (idx == NN - 1) g_rowptr[NN] = blockoff + sm.sc.s[tid];
        }
    }
    gbar();

    // ---- Phase 3: CSR fill ----
    for (int t = gtid; t < EE / 4; t += stride) {
        int4 s4 = ((const int4*)src)[t];
        int4 d4 = ((const int4*)dst)[t];
        int p0 = atomicAdd(&g_cursor[d4.x], 1);
        int p1 = atomicAdd(&g_cursor[d4.y], 1);
        int p2 = atomicAdd(&g_cursor[d4.z], 1);
        int p3 = atomicAdd(&g_cursor[d4.w], 1);
        g_csr[p0] = make_int2(s4.x, __float_as_int(g_dinv[s4.x]));
        g_csr[p1] = make_int2(s4.y, __float_as_int(g_dinv[s4.y]));
        g_csr[p2] = make_int2(s4.z, __float_as_int(g_dinv[s4.z]));
        g_csr[p3] = make_int2(s4.w, __float_as_int(g_dinv[s4.w]));
    }
    gbar();

    // ---- Phase 4: aggregate layer 1 (+ BN stats) ----
    agg_nodes<0>(g_h1, g_agg, b1, batch, sm);
    gbar();

    // ---- Phase 5: GEMM-2 with fused BN finalize + BN/ELU on load ----
    if (tid < 64) {
        float inv_n = 1.0f / (float)NN;
        float mu  = g_bnsum[tid] * inv_n;
        float var = g_bnsq[tid] * inv_n - mu * mu;
        float sc  = gamma[tid] * rsqrtf(var + BN_EPS);
        sm.g.scale[tid] = sc;
        sm.g.shift[tid] = beta[tid] - mu * sc;
    }
    for (int tile = blockIdx.x; tile < NTILES; tile += gridDim.x)
        gemm_tile<1>(tile, g_agg, W2, g_h2, sm);
    gbar();

    // ---- Phase 6: aggregate layer 2 (+ fused mean pool) ----
    agg_nodes<1>(g_h2, out, b2, batch, sm);
    gbar();

    // ---- Phase 7: pool divide ----
    if (blockIdx.x == 0) {
        float* rep = out + (size_t)NN * D;
        for (int t = tid; t < GG * D; t += 256) {
            int g = t >> 6;
            rep[t] = g_pool[t] / fmaxf(g_cnt[g], 1.0f);
        }
    }
}

// ---------------- launch ----------------
extern "C" void kernel_launch(void* const* d_in, const int* in_sizes, int n_in,
                              void* d_out, int out_size) {
    const float* x     = (const float*)d_in[0];
    const int*   ei    = (const int*)  d_in[1];
    const int*   batch = (const int*)  d_in[2];
    const float* W1    = (const float*)d_in[3];
    const float* b1    = (const float*)d_in[4];
    const float* gamma = (const float*)d_in[5];
    const float* beta  = (const float*)d_in[6];
    const float* W2    = (const float*)d_in[7];
    const float* b2    = (const float*)d_in[8];
    float* out = (float*)d_out;
    const int* src = ei;
    const int* dst = ei + EE;

    // Co-resident grid: required for the software grid barrier.
    int dev = 0;
    cudaGetDevice(&dev);
    int nsm = 148;
    cudaDeviceGetAttribute(&nsm, cudaDevAttrMultiProcessorCount, dev);
    int maxb = 1;
    cudaOccupancyMaxActiveBlocksPerMultiprocessor(&maxb, mega_kernel, 256, 0);
    if (maxb < 1) maxb = 1;
    int grid = nsm * maxb;

    mega_kernel<<<grid, 256>>>(x, src, dst, batch, W1, b1, gamma, beta, W2, b2, out);
}

// round 10
// speedup vs baseline: 1.0395x; 1.0395x over previous
#include <cuda_runtime.h>
#include <math.h>

#define NN 50000
#define EE 800000
#define D  64
#define GG 64
#define BN_EPS 1e-5f
#define SCAN_BLOCKS 196   // ceil(50000/256)

// ---------------- device scratch (device-code access only) ----------------
__device__ int   g_degi  [NN];          // zero at load; re-zeroed by scan23 each call
__device__ float g_dinv  [NN];
__device__ int   g_rowptr[NN + 1];
__device__ int   g_cursor[NN];
__device__ int   g_blocksum[256];
__device__ int   g_done = 0;            // ticket counter for fused pool_div
__device__ __align__(16) int2  g_csr[EE + NN];  // (src, dinv[src] bits), even-padded
__device__ __align__(16) float g_h1 [NN * D];
__device__ __align__(16) float g_agg[NN * D];
__device__ __align__(16) float g_h2 [NN * D];
__device__ float g_bnsum[D];
__device__ float g_bnsq [D];
__device__ __align__(16) float g_pool[GG * D];
__device__ float g_cnt [GG];

// ---------------- packed f32x2 helpers ----------------
__device__ __forceinline__ unsigned long long pack2(float x, float y) {
    unsigned long long r;
    asm("mov.b64 %0, {%1, %2};" : "=l"(r) : "f"(x), "f"(y));
    return r;
}
__device__ __forceinline__ void ffma2(unsigned long long& d,
                                      unsigned long long a, unsigned long long b) {
    asm("fma.rn.f32x2 %0, %1, %2, %0;" : "+l"(d) : "l"(a), "l"(b));
}
__device__ __forceinline__ float2 unpack2(unsigned long long v) {
    float2 f;
    asm("mov.b64 {%0, %1}, %2;" : "=f"(f.x), "=f"(f.y) : "l"(v));
    return f;
}

// ---------------- zero small accumulators (runs on side stream) ----------------
__global__ void zero_kernel() {
    int i = blockIdx.x * blockDim.x + threadIdx.x;
    if (i < GG * D) g_pool[i] = 0.f;
    if (i < D)    { g_bnsum[i] = 0.f; g_bnsq[i] = 0.f; }
    if (i < GG)     g_cnt[i] = 0.f;
}

// ---------------- degree: 4 edges per thread ----------------
__global__ void degree_kernel(const int* __restrict__ dst) {
    int t = blockIdx.x * blockDim.x + threadIdx.x;
    if (t * 4 >= EE) return;
    int4 d4 = ((const int4*)dst)[t];
    atomicAdd(&g_degi[d4.x], 1);
    atomicAdd(&g_degi[d4.y], 1);
    atomicAdd(&g_degi[d4.z], 1);
    atomicAdd(&g_degi[d4.w], 1);
}

// ---------------- scan phase 1: padded block sums (+ fused dinv) ----------------
__global__ void scan1_kernel() {
    __shared__ int s[256];
    int idx = blockIdx.x * 256 + threadIdx.x;
    int dv = (idx < NN) ? g_degi[idx] : 0;
    if (idx < NN) g_dinv[idx] = rsqrtf((float)dv + 1.0f);
    s[threadIdx.x] = (dv + 1) & ~1;               // pad degree to even
    __syncthreads();
    for (int o = 128; o > 0; o >>= 1) {
        if (threadIdx.x < o) s[threadIdx.x] += s[threadIdx.x + o];
        __syncthreads();
    }
    if (threadIdx.x == 0) g_blocksum[blockIdx.x] = s[0];
}

// ---------------- scan 2+3 fused: rowptr/cursor, pad slot, degi reset ----------------
__global__ void scan23_kernel() {
    __shared__ int sb[256];
    __shared__ int s[256];
    int t = threadIdx.x;
    sb[t] = (t < SCAN_BLOCKS) ? g_blocksum[t] : 0;
    __syncthreads();
    for (int o = 1; o < 256; o <<= 1) {
        int a = (t >= o) ? sb[t - o] : 0;
        __syncthreads();
        sb[t] += a;
        __syncthreads();
    }
    int blockoff = (blockIdx.x == 0) ? 0 : sb[blockIdx.x - 1];
    int idx = blockIdx.x * 256 + t;
    int v  = (idx < NN) ? g_degi[idx] : 0;
    int vp = (v + 1) & ~1;
    s[t] = vp;
    __syncthreads();
    for (int o = 1; o < 256; o <<= 1) {
        int a = (t >= o) ? s[t - o] : 0;
        __syncthreads();
        s[t] += a;
        __syncthreads();
    }
    if (idx < NN) {
        int rp = blockoff + s[t] - vp;
        g_rowptr[idx] = rp;
        g_cursor[idx] = rp;
        if (v & 1) g_csr[rp + v] = make_int2(0, 0);  // zero pad entry
        g_degi[idx] = 0;                             // invariant for next call
        if (idx == NN - 1) g_rowptr[NN] = blockoff + s[t];
    }
}

// ---------------- CSR fill: 4 edges/thread, stores (src, dinv[src]) ----------------
__global__ void csr_fill_kernel(const int* __restrict__ src,
                                const int* __restrict__ dst) {
    int t = blockIdx.x * blockDim.x + threadIdx.x;
    if (t * 4 >= EE) return;
    int4 s4 = ((const int4*)src)[t];
    int4 d4 = ((const int4*)dst)[t];
    int p0 = atomicAdd(&g_cursor[d4.x], 1);
    int p1 = atomicAdd(&g_cursor[d4.y], 1);
    int p2 = atomicAdd(&g_cursor[d4.z], 1);
    int p3 = atomicAdd(&g_cursor[d4.w], 1);
    g_csr[p0] = make_int2(s4.x, __float_as_int(g_dinv[s4.x]));
    g_csr[p1] = make_int2(s4.y, __float_as_int(g_dinv[s4.y]));
    g_csr[p2] = make_int2(s4.z, __float_as_int(g_dinv[s4.z]));
    g_csr[p3] = make_int2(s4.w, __float_as_int(g_dinv[s4.w]));
}

// ---------------- GEMM: 256 threads, 4x4 outputs/thread, f32x2 inner math ------------
template<int MODE>
__global__ void gemm64_kernel(const float* __restrict__ Xp,
                              const float* __restrict__ W,
                              const float* __restrict__ gamma,
                              const float* __restrict__ beta) {
    const float* __restrict__ X = (MODE == 0) ? Xp : (const float*)g_agg;
    float* __restrict__       Y = (MODE == 0) ? g_h1 : g_h2;

    __shared__ float sX[64][65];
    __shared__ __align__(16) float sW[64][64];
    __shared__ float s_scale[64], s_shift[64];

    int tid  = threadIdx.y * 16 + threadIdx.x;
    int row0 = blockIdx.x * 64;

    if (MODE == 1) {
        if (tid < 64) {
            float inv_n = 1.0f / (float)NN;
            float mu  = g_bnsum[tid] * inv_n;
            float var = g_bnsq[tid] * inv_n - mu * mu;
            float sc  = gamma[tid] * rsqrtf(var + BN_EPS);
            s_scale[tid] = sc;
            s_shift[tid] = beta[tid] - mu * sc;
        }
        __syncthreads();
    }

    #pragma unroll
    for (int t = tid * 4; t < 4096; t += 1024) {
        *(float4*)(&sW[t >> 6][t & 63]) = *(const float4*)(W + t);
    }
    #pragma unroll
    for (int t = tid * 4; t < 4096; t += 1024) {
        int r = t >> 6, c = t & 63;
        float4 v = make_float4(0.f, 0.f, 0.f, 0.f);
        if (row0 + r < NN) v = *(const float4*)(X + (size_t)(row0 + r) * D + c);
        if (MODE == 1) {
            v.x = v.x * s_scale[c]     + s_shift[c];
            v.y = v.y * s_scale[c + 1] + s_shift[c + 1];
            v.z = v.z * s_scale[c + 2] + s_shift[c + 2];
            v.w = v.w * s_scale[c + 3] + s_shift[c + 3];
            v.x = (v.x > 0.f) ? v.x : (__expf(v.x) - 1.0f);
            v.y = (v.y > 0.f) ? v.y : (__expf(v.y) - 1.0f);
            v.z = (v.z > 0.f) ? v.z : (__expf(v.z) - 1.0f);
            v.w = (v.w > 0.f) ? v.w : (__expf(v.w) - 1.0f);
        }
        sX[r][c] = v.x; sX[r][c + 1] = v.y; sX[r][c + 2] = v.z; sX[r][c + 3] = v.w;
    }
    __syncthreads();

    // 4 rows x 4 cols per thread; accumulate as 4x2 f32x2 packs
    unsigned long long acc[4][2] = {};
    int c0 = threadIdx.x * 4, r0 = threadIdx.y * 4;
    #pragma unroll 16
    for (int k = 0; k < 64; k++) {
        float4 w = *(const float4*)(&sW[k][c0]);
        unsigned long long w01 = pack2(w.x, w.y);
        unsigned long long w23 = pack2(w.z, w.w);
        #pragma unroll
        for (int r = 0; r < 4; r++) {
            float xv = sX[r0 + r][k];
            unsigned long long xx = pack2(xv, xv);
            ffma2(acc[r][0], xx, w01);
            ffma2(acc[r][1], xx, w23);
        }
    }
    #pragma unroll
    for (int r = 0; r < 4; r++) {
        int row = row0 + r0 + r;
        if (row < NN) {
            float2 p0 = unpack2(acc[r][0]), p1 = unpack2(acc[r][1]);
            *(float4*)(Y + (size_t)row * D + c0) = make_float4(p0.x, p0.y, p1.x, p1.y);
        }
    }
}

// ---------------- gather aggregation: warp/node, half-warps (R8 proven layout) -------
// MODE 0: h=g_h1 -> g_agg (no atomics).  MODE 1: h=g_h2 -> outp + pool + fused pool_div.
template<int MODE>
__global__ void aggregate_kernel(float* __restrict__ outp,
                                 const float* __restrict__ bias,
                                 const int* __restrict__ batch) {
    const float* __restrict__ h = (MODE == 0) ? g_h1 : g_h2;
    float* __restrict__ dstbuf  = (MODE == 0) ? g_agg : outp;

    int n    = (blockIdx.x * blockDim.x + threadIdx.x) >> 5;  // grid: n < NN
    int lane = threadIdx.x & 31;
    int half = lane >> 4;
    int fl   = lane & 15;

    int e0 = g_rowptr[n];
    int e1 = g_rowptr[n + 1];     // padded even length

    unsigned long long a0 = 0ull, a1 = 0ull;
    #pragma unroll 8
    for (int e = e0 + half; e < e1; e += 2) {
        int2 ec = g_csr[e];
        float c = __int_as_float(ec.y);             // dinv[src]
        float4 v = ((const float4*)h)[(size_t)ec.x * 16 + fl];
        unsigned long long cc = pack2(c, c);
        ffma2(a0, cc, pack2(v.x, v.y));
        ffma2(a1, cc, pack2(v.z, v.w));
    }
    float2 f0 = unpack2(a0), f1 = unpack2(a1);
    float4 acc = make_float4(f0.x, f0.y, f1.x, f1.y);
    acc.x += __shfl_xor_sync(0xffffffffu, acc.x, 16);
    acc.y += __shfl_xor_sync(0xffffffffu, acc.y, 16);
    acc.z += __shfl_xor_sync(0xffffffffu, acc.z, 16);
    acc.w += __shfl_xor_sync(0xffffffffu, acc.w, 16);

    float di = g_dinv[n];
    float cs = di * di;
    if (half == 0) {
        float4 hv = ((const float4*)h)[(size_t)n * 16 + fl];
        float4 bv = ((const float4*)bias)[fl];
        acc.x = fmaf(di, acc.x, fmaf(cs, hv.x, bv.x));
        acc.y = fmaf(di, acc.y, fmaf(cs, hv.y, bv.y));
        acc.z = fmaf(di, acc.z, fmaf(cs, hv.z, bv.z));
        acc.w = fmaf(di, acc.w, fmaf(cs, hv.w, bv.w));
        ((float4*)dstbuf)[(size_t)n * 16 + fl] = acc;

        if (MODE == 1) {
            int g = batch[n];
            if (fl == 0) atomicAdd(&g_cnt[g], 1.0f);
            atomicAdd(((float4*)g_pool) + (size_t)g * 16 + fl, acc);
        }
    }

    if (MODE == 1) {
        // last-block ticket: fused pool_div (deterministic, self-resetting)
        __shared__ int s_last;
        __threadfence();
        __syncthreads();
        if (threadIdx.x == 0) {
            int ticket = atomicAdd(&g_done, 1);
            s_last = (ticket == (int)gridDim.x - 1) ? 1 : 0;
        }
        __syncthreads();
        if (s_last) {
            __threadfence();
            float* rep = outp + (size_t)NN * D;
            for (int t = threadIdx.x; t < GG * D; t += 256) {
                int g = t >> 6;
                float pv = __ldcg(&g_pool[t]);
                float cv = __ldcg(&g_cnt[g]);
                rep[t] = pv / fmaxf(cv, 1.0f);
            }
            if (threadIdx.x == 0) g_done = 0;   // reset for next replay
        }
    }
}

// ---------------- BN statistics: one streaming pass over g_agg ----------------
__global__ void bnstats_kernel() {
    int tid    = blockIdx.x * blockDim.x + threadIdx.x;
    int stride = gridDim.x * blockDim.x;
    float sum = 0.f, sq = 0.f;
    for (int idx = tid; idx < NN * D; idx += stride) {
        float v = g_agg[idx];
        sum += v; sq += v * v;
    }
    __shared__ float s_sum[256], s_sq[256];
    s_sum[threadIdx.x] = sum; s_sq[threadIdx.x] = sq;
    __syncthreads();
    if (threadIdx.x < 64) {
        float ts = s_sum[threadIdx.x] + s_sum[threadIdx.x + 64] +
                   s_sum[threadIdx.x + 128] + s_sum[threadIdx.x + 192];
        float tq = s_sq[threadIdx.x] + s_sq[threadIdx.x + 64] +
                   s_sq[threadIdx.x + 128] + s_sq[threadIdx.x + 192];
        atomicAdd(&g_bnsum[threadIdx.x], ts);
        atomicAdd(&g_bnsq [threadIdx.x], tq);
    }
}

// ---------------- side stream for capture-time fork/join ----------------
struct SideCtx {
    cudaStream_t s2;
    cudaEvent_t evFork, evJoin;
    SideCtx() {
        cudaStreamCreateWithFlags(&s2, cudaStreamNonBlocking);
        cudaEventCreateWithFlags(&evFork, cudaEventDisableTiming);
        cudaEventCreateWithFlags(&evJoin, cudaEventDisableTiming);
    }
};
static SideCtx g_side;

// ---------------- launch ----------------
extern "C" void kernel_launch(void* const* d_in, const int* in_sizes, int n_in,
                              void* d_out, int out_size) {
    const float* x     = (const float*)d_in[0];
    const int*   ei    = (const int*)  d_in[1];
    const int*   batch = (const int*)  d_in[2];
    const float* W1    = (const float*)d_in[3];
    const float* b1    = (const float*)d_in[4];
    const float* gamma = (const float*)d_in[5];
    const float* beta  = (const float*)d_in[6];
    const float* W2    = (const float*)d_in[7];
    const float* b2    = (const float*)d_in[8];
    float* out = (float*)d_out;
    const int* src = ei;
    const int* dst = ei + EE;

    const int TPB = 256;
    int e4_blocks   = (EE / 4 + TPB - 1) / TPB;        // 782
    int gemm_blocks = (NN + 63) / 64;                  // 782
    int agg_blocks  = NN / 8;                          // 6250

    // Fork: zero + GEMM-1 run concurrently with the CSR build.
    cudaEventRecord(g_side.evFork, 0);
    cudaStreamWaitEvent(g_side.s2, g_side.evFork, 0);
    zero_kernel<<<16, TPB, 0, g_side.s2>>>();
    gemm64_kernel<0><<<gemm_blocks, dim3(16, 16), 0, g_side.s2>>>(x, W1, gamma, beta);
    cudaEventRecord(g_side.evJoin, g_side.s2);

    // Main branch: CSR build (g_degi is zero on entry — invariant)
    degree_kernel<<<e4_blocks, TPB>>>(dst);
    scan1_kernel<<<SCAN_BLOCKS, 256>>>();
    scan23_kernel<<<SCAN_BLOCKS, 256>>>();
    csr_fill_kernel<<<e4_blocks, TPB>>>(src, dst);

    // Join, then the serial tail
    cudaStreamWaitEvent(0, g_side.evJoin, 0);
    aggregate_kernel<0><<<agg_blocks, TPB>>>(out, b1, batch);
    bnstats_kernel<<<1184, TPB>>>();
    gemm64_kernel<1><<<gemm_blocks, dim3(16, 16)>>>(x, W2, gamma, beta);
    aggregate_kernel<1><<<agg_blocks, TPB>>>(out, b2, batch);
}

// round 11
// speedup vs baseline: 1.1214x; 1.0788x over previous
#include <cuda_runtime.h>
#include <math.h>

#define NN 50000
#define EE 800000
#define D  64
#define GG 64
#define BN_EPS 1e-5f
#define SCAN_BLOCKS 196   // ceil(50000/256)
#define AGG0_BLOCKS 1184  // 148 SMs * 8 blocks

// ---------------- device scratch (device-code access only) ----------------
__device__ int   g_degi  [NN];          // zero at load; re-zeroed by scan23 each call
__device__ float g_dinv  [NN];
__device__ int   g_rowptr[NN + 1];
__device__ int   g_cursor[NN];
__device__ int   g_blocksum[256];
__device__ __align__(16) int2  g_csr[EE + NN];  // (src, dinv[src] bits), even-padded
__device__ __align__(16) float g_h1 [NN * D];
__device__ __align__(16) float g_agg[NN * D];
__device__ __align__(16) float g_h2 [NN * D];
__device__ float g_bnsum[D];
__device__ float g_bnsq [D];
__device__ __align__(16) float g_pool[GG * D];
__device__ float g_cnt [GG];

// ---------------- packed f32x2 helpers (aggregate inner loop only) ----------------
__device__ __forceinline__ unsigned long long pack2(float x, float y) {
    unsigned long long r;
    asm("mov.b64 %0, {%1, %2};" : "=l"(r) : "f"(x), "f"(y));
    return r;
}
__device__ __forceinline__ void ffma2(unsigned long long& d,
                                      unsigned long long a, unsigned long long b) {
    asm("fma.rn.f32x2 %0, %1, %2, %0;" : "+l"(d) : "l"(a), "l"(b));
}
__device__ __forceinline__ float2 unpack2(unsigned long long v) {
    float2 f;
    asm("mov.b64 {%0, %1}, %2;" : "=f"(f.x), "=f"(f.y) : "l"(v));
    return f;
}

// ---------------- zero small accumulators (runs on side stream) ----------------
__global__ void zero_kernel() {
    int i = blockIdx.x * blockDim.x + threadIdx.x;
    if (i < GG * D) g_pool[i] = 0.f;
    if (i < D)    { g_bnsum[i] = 0.f; g_bnsq[i] = 0.f; }
    if (i < GG)     g_cnt[i] = 0.f;
}

// ---------------- degree: 4 edges per thread ----------------
__global__ void degree_kernel(const int* __restrict__ dst) {
    int t = blockIdx.x * blockDim.x + threadIdx.x;
    if (t * 4 >= EE) return;
    int4 d4 = ((const int4*)dst)[t];
    atomicAdd(&g_degi[d4.x], 1);
    atomicAdd(&g_degi[d4.y], 1);
    atomicAdd(&g_degi[d4.z], 1);
    atomicAdd(&g_degi[d4.w], 1);
}

// ---------------- scan phase 1: padded block sums (+ fused dinv) ----------------
__global__ void scan1_kernel() {
    __shared__ int s[256];
    int idx = blockIdx.x * 256 + threadIdx.x;
    int dv = (idx < NN) ? g_degi[idx] : 0;
    if (idx < NN) g_dinv[idx] = rsqrtf((float)dv + 1.0f);
    s[threadIdx.x] = (dv + 1) & ~1;               // pad degree to even
    __syncthreads();
    for (int o = 128; o > 0; o >>= 1) {
        if (threadIdx.x < o) s[threadIdx.x] += s[threadIdx.x + o];
        __syncthreads();
    }
    if (threadIdx.x == 0) g_blocksum[blockIdx.x] = s[0];
}

// ---------------- scan 2+3 fused: rowptr/cursor, pad slot, degi reset ----------------
__global__ void scan23_kernel() {
    __shared__ int sb[256];
    __shared__ int s[256];
    int t = threadIdx.x;
    sb[t] = (t < SCAN_BLOCKS) ? g_blocksum[t] : 0;
    __syncthreads();
    for (int o = 1; o < 256; o <<= 1) {
        int a = (t >= o) ? sb[t - o] : 0;
        __syncthreads();
        sb[t] += a;
        __syncthreads();
    }
    int blockoff = (blockIdx.x == 0) ? 0 : sb[blockIdx.x - 1];
    int idx = blockIdx.x * 256 + t;
    int v  = (idx < NN) ? g_degi[idx] : 0;
    int vp = (v + 1) & ~1;
    s[t] = vp;
    __syncthreads();
    for (int o = 1; o < 256; o <<= 1) {
        int a = (t >= o) ? s[t - o] : 0;
        __syncthreads();
        s[t] += a;
        __syncthreads();
    }
    if (idx < NN) {
        int rp = blockoff + s[t] - vp;
        g_rowptr[idx] = rp;
        g_cursor[idx] = rp;
        if (v & 1) g_csr[rp + v] = make_int2(0, 0);  // zero pad entry
        g_degi[idx] = 0;                             // invariant for next call
        if (idx == NN - 1) g_rowptr[NN] = blockoff + s[t];
    }
}

// ---------------- CSR fill: 4 edges/thread, stores (src, dinv[src]) ----------------
__global__ void csr_fill_kernel(const int* __restrict__ src,
                                const int* __restrict__ dst) {
    int t = blockIdx.x * blockDim.x + threadIdx.x;
    if (t * 4 >= EE) return;
    int4 s4 = ((const int4*)src)[t];
    int4 d4 = ((const int4*)dst)[t];
    int p0 = atomicAdd(&g_cursor[d4.x], 1);
    int p1 = atomicAdd(&g_cursor[d4.y], 1);
    int p2 = atomicAdd(&g_cursor[d4.z], 1);
    int p3 = atomicAdd(&g_cursor[d4.w], 1);
    g_csr[p0] = make_int2(s4.x, __float_as_int(g_dinv[s4.x]));
    g_csr[p1] = make_int2(s4.y, __float_as_int(g_dinv[s4.y]));
    g_csr[p2] = make_int2(s4.z, __float_as_int(g_dinv[s4.z]));
    g_csr[p3] = make_int2(s4.w, __float_as_int(g_dinv[s4.w]));
}

// ---------------- GEMM: R8 proven shape (256 threads, scalar FFMA) ----------------
template<int MODE>
__global__ void gemm64_kernel(const float* __restrict__ Xp,
                              const float* __restrict__ W,
                              const float* __restrict__ gamma,
                              const float* __restrict__ beta) {
    const float* __restrict__ X = (MODE == 0) ? Xp : (const float*)g_agg;
    float* __restrict__       Y = (MODE == 0) ? g_h1 : g_h2;

    __shared__ float sX[64][65];
    __shared__ __align__(16) float sW[64][64];
    __shared__ float s_scale[64], s_shift[64];

    int tid  = threadIdx.y * 16 + threadIdx.x;
    int row0 = blockIdx.x * 64;

    if (MODE == 1) {
        if (tid < 64) {
            float inv_n = 1.0f / (float)NN;
            float mu  = g_bnsum[tid] * inv_n;
            float var = g_bnsq[tid] * inv_n - mu * mu;
            float sc  = gamma[tid] * rsqrtf(var + BN_EPS);
            s_scale[tid] = sc;
            s_shift[tid] = beta[tid] - mu * sc;
        }
        __syncthreads();
    }

    #pragma unroll
    for (int t = tid * 4; t < 4096; t += 1024) {
        *(float4*)(&sW[t >> 6][t & 63]) = *(const float4*)(W + t);
    }
    #pragma unroll
    for (int t = tid * 4; t < 4096; t += 1024) {
        int r = t >> 6, c = t & 63;
        float4 v = make_float4(0.f, 0.f, 0.f, 0.f);
        if (row0 + r < NN) v = *(const float4*)(X + (size_t)(row0 + r) * D + c);
        if (MODE == 1) {
            v.x = v.x * s_scale[c]     + s_shift[c];
            v.y = v.y * s_scale[c + 1] + s_shift[c + 1];
            v.z = v.z * s_scale[c + 2] + s_shift[c + 2];
            v.w = v.w * s_scale[c + 3] + s_shift[c + 3];
            v.x = (v.x > 0.f) ? v.x : (__expf(v.x) - 1.0f);
            v.y = (v.y > 0.f) ? v.y : (__expf(v.y) - 1.0f);
            v.z = (v.z > 0.f) ? v.z : (__expf(v.z) - 1.0f);
            v.w = (v.w > 0.f) ? v.w : (__expf(v.w) - 1.0f);
        }
        sX[r][c] = v.x; sX[r][c + 1] = v.y; sX[r][c + 2] = v.z; sX[r][c + 3] = v.w;
    }
    __syncthreads();

    float acc[4][4] = {};
    int c0 = threadIdx.x * 4, r0 = threadIdx.y * 4;
    #pragma unroll 16
    for (int k = 0; k < 64; k++) {
        float4 w = *(const float4*)(&sW[k][c0]);
        #pragma unroll
        for (int r = 0; r < 4; r++) {
            float xv = sX[r0 + r][k];
            acc[r][0] += xv * w.x; acc[r][1] += xv * w.y;
            acc[r][2] += xv * w.z; acc[r][3] += xv * w.w;
        }
    }
    #pragma unroll
    for (int r = 0; r < 4; r++) {
        int row = row0 + r0 + r;
        if (row < NN)
            *(float4*)(Y + (size_t)row * D + c0) =
                make_float4(acc[r][0], acc[r][1], acc[r][2], acc[r][3]);
    }
}

// ---------------- aggregate layer 1: grid-strided nodes + fused BN stats -------------
// Inner loop identical to R8. Each warp handles ~NN/(AGG0_BLOCKS*8) nodes; BN stats
// accumulate in registers; one atomic-free staged block reduction at the end.
__global__ void aggregate0_kernel(const float* __restrict__ bias) {
    __shared__ float s_sum[8][64];
    __shared__ float s_sq [8][64];

    int warp = threadIdx.x >> 5;
    int lane = threadIdx.x & 31;
    int half = lane >> 4;
    int fl   = lane & 15;

    float4 bv = ((const float4*)bias)[fl];
    float bns[4] = {0.f, 0.f, 0.f, 0.f};
    float bnq[4] = {0.f, 0.f, 0.f, 0.f};

    for (int n = blockIdx.x * 8 + warp; n < NN; n += AGG0_BLOCKS * 8) {
        int e0 = g_rowptr[n];
        int e1 = g_rowptr[n + 1];     // padded even length

        unsigned long long a0 = 0ull, a1 = 0ull;
        #pragma unroll 4
        for (int e = e0 + half; e < e1; e += 2) {
            int2 ec = g_csr[e];
            float c = __int_as_float(ec.y);             // dinv[src]
            float4 v = ((const float4*)g_h1)[(size_t)ec.x * 16 + fl];
            unsigned long long cc = pack2(c, c);
            ffma2(a0, cc, pack2(v.x, v.y));
            ffma2(a1, cc, pack2(v.z, v.w));
        }
        float2 f0 = unpack2(a0), f1 = unpack2(a1);
        float4 acc = make_float4(f0.x, f0.y, f1.x, f1.y);
        acc.x += __shfl_xor_sync(0xffffffffu, acc.x, 16);
        acc.y += __shfl_xor_sync(0xffffffffu, acc.y, 16);
        acc.z += __shfl_xor_sync(0xffffffffu, acc.z, 16);
        acc.w += __shfl_xor_sync(0xffffffffu, acc.w, 16);

        if (half == 0) {
            float di = g_dinv[n];
            float cs = di * di;
            float4 hv = ((const float4*)g_h1)[(size_t)n * 16 + fl];
            acc.x = fmaf(di, acc.x, fmaf(cs, hv.x, bv.x));
            acc.y = fmaf(di, acc.y, fmaf(cs, hv.y, bv.y));
            acc.z = fmaf(di, acc.z, fmaf(cs, hv.z, bv.z));
            acc.w = fmaf(di, acc.w, fmaf(cs, hv.w, bv.w));
            ((float4*)g_agg)[(size_t)n * 16 + fl] = acc;

            bns[0] += acc.x; bns[1] += acc.y; bns[2] += acc.z; bns[3] += acc.w;
            bnq[0] += acc.x * acc.x; bnq[1] += acc.y * acc.y;
            bnq[2] += acc.z * acc.z; bnq[3] += acc.w * acc.w;
        }
    }

    // staged (atomic-free) block reduction: warp -> smem row, then 64 threads fold
    if (half == 0) {
        #pragma unroll
        for (int i = 0; i < 4; i++) {
            s_sum[warp][fl * 4 + i] = bns[i];
            s_sq [warp][fl * 4 + i] = bnq[i];
        }
    }
    __syncthreads();
    if (threadIdx.x < 64) {
        float ts = 0.f, tq = 0.f;
        #pragma unroll
        for (int w = 0; w < 8; w++) { ts += s_sum[w][threadIdx.x]; tq += s_sq[w][threadIdx.x]; }
        atomicAdd(&g_bnsum[threadIdx.x], ts);
        atomicAdd(&g_bnsq [threadIdx.x], tq);
    }
}

// ---------------- aggregate layer 2: R8 exact (warp per node + fused pool) -----------
__global__ void aggregate1_kernel(float* __restrict__ outp,
                                  const float* __restrict__ bias,
                                  const int* __restrict__ batch) {
    int n    = (blockIdx.x * blockDim.x + threadIdx.x) >> 5;  // grid: n < NN
    int lane = threadIdx.x & 31;
    int half = lane >> 4;
    int fl   = lane & 15;

    int e0 = g_rowptr[n];
    int e1 = g_rowptr[n + 1];

    unsigned long long a0 = 0ull, a1 = 0ull;
    #pragma unroll 4
    for (int e = e0 + half; e < e1; e += 2) {
        int2 ec = g_csr[e];
        float c = __int_as_float(ec.y);
        float4 v = ((const float4*)g_h2)[(size_t)ec.x * 16 + fl];
        unsigned long long cc = pack2(c, c);
        ffma2(a0, cc, pack2(v.x, v.y));
        ffma2(a1, cc, pack2(v.z, v.w));
    }
    float2 f0 = unpack2(a0), f1 = unpack2(a1);
    float4 acc = make_float4(f0.x, f0.y, f1.x, f1.y);
    acc.x += __shfl_xor_sync(0xffffffffu, acc.x, 16);
    acc.y += __shfl_xor_sync(0xffffffffu, acc.y, 16);
    acc.z += __shfl_xor_sync(0xffffffffu, acc.z, 16);
    acc.w += __shfl_xor_sync(0xffffffffu, acc.w, 16);

    float di = g_dinv[n];
    float cs = di * di;
    if (half == 0) {
        float4 hv = ((const float4*)g_h2)[(size_t)n * 16 + fl];
        float4 bv = ((const float4*)bias)[fl];
        acc.x = fmaf(di, acc.x, fmaf(cs, hv.x, bv.x));
        acc.y = fmaf(di, acc.y, fmaf(cs, hv.y, bv.y));
        acc.z = fmaf(di, acc.z, fmaf(cs, hv.z, bv.z));
        acc.w = fmaf(di, acc.w, fmaf(cs, hv.w, bv.w));
        ((float4*)outp)[(size_t)n * 16 + fl] = acc;

        int g = batch[n];
        if (fl == 0) atomicAdd(&g_cnt[g], 1.0f);
        atomicAdd(((float4*)g_pool) + (size_t)g * 16 + fl, acc);
    }
}

__global__ void pool_div_kernel(float* __restrict__ rep) {
    int t = blockIdx.x * blockDim.x + threadIdx.x;
    if (t >= GG * D) return;
    int g = t >> 6;
    rep[t] = g_pool[t] / fmaxf(g_cnt[g], 1.0f);
}

// ---------------- side stream for capture-time fork/join ----------------
struct SideCtx {
    cudaStream_t s2;
    cudaEvent_t evFork, evJoin;
    SideCtx() {
        cudaStreamCreateWithFlags(&s2, cudaStreamNonBlocking);
        cudaEventCreateWithFlags(&evFork, cudaEventDisableTiming);
        cudaEventCreateWithFlags(&evJoin, cudaEventDisableTiming);
    }
};
static SideCtx g_side;

// ---------------- launch ----------------
extern "C" void kernel_launch(void* const* d_in, const int* in_sizes, int n_in,
                              void* d_out, int out_size) {
    const float* x     = (const float*)d_in[0];
    const int*   ei    = (const int*)  d_in[1];
    const int*   batch = (const int*)  d_in[2];
    const float* W1    = (const float*)d_in[3];
    const float* b1    = (const float*)d_in[4];
    const float* gamma = (const float*)d_in[5];
    const float* beta  = (const float*)d_in[6];
    const float* W2    = (const float*)d_in[7];
    const float* b2    = (const float*)d_in[8];
    float* out = (float*)d_out;
    const int* src = ei;
    const int* dst = ei + EE;

    const int TPB = 256;
    int e4_blocks   = (EE / 4 + TPB - 1) / TPB;        // 782
    int gemm_blocks = (NN + 63) / 64;                  // 782
    int agg1_blocks = NN / 8;                          // 6250 (warp per node)

    // Fork: zero + GEMM-1 run concurrently with the CSR build.
    cudaEventRecord(g_side.evFork, 0);
    cudaStreamWaitEvent(g_side.s2, g_side.evFork, 0);
    zero_kernel<<<16, TPB, 0, g_side.s2>>>();
    gemm64_kernel<0><<<gemm_blocks, dim3(16, 16), 0, g_side.s2>>>(x, W1, gamma, beta);
    cudaEventRecord(g_side.evJoin, g_side.s2);

    // Main branch: CSR build (g_degi is zero on entry — invariant)
    degree_kernel<<<e4_blocks, TPB>>>(dst);
    scan1_kernel<<<SCAN_BLOCKS, 256>>>();
    scan23_kernel<<<SCAN_BLOCKS, 256>>>();
    csr_fill_kernel<<<e4_blocks, TPB>>>(src, dst);

    // Join, then the serial tail (agg0 now carries BN stats — no bnstats pass)
    cudaStreamWaitEvent(0, g_side.evJoin, 0);
    aggregate0_kernel<<<AGG0_BLOCKS, TPB>>>(b1);
    gemm64_kernel<1><<<gemm_blocks, dim3(16, 16)>>>(x, W2, gamma, beta);
    aggregate1_kernel<<<agg1_blocks, TPB>>>(out, b2, batch);
    pool_div_kernel<<<16, TPB>>>(out + (size_t)NN * D);
}